// round 1
// baseline (speedup 1.0000x reference)
#include <cuda_runtime.h>
#include <cuda_bf16.h>
#include <cstdint>

#define N_USERS 100000
#define N_ITEMS 50000
#define N_NODES (N_USERS + N_ITEMS)
#define EMB 64
#define BATCH 4096

// ---- static scratch (no allocations allowed) ----
__device__ float g_repA[(size_t)N_NODES * EMB];  // 38.4 MB
__device__ float g_repB[(size_t)N_NODES * EMB];  // 38.4 MB
__device__ float g_acc [(size_t)N_NODES * EMB];  // 38.4 MB
__device__ float g_deg [N_NODES];
__device__ float g_dinv[N_NODES];

// ---------------------------------------------------------------------------
// degree histogram: each interaction bumps deg[u] and deg[item]
__global__ void k_hist(const int* __restrict__ eu, const int* __restrict__ ei,
                       float* __restrict__ deg, int E) {
    int i = blockIdx.x * blockDim.x + threadIdx.x;
    if (i >= E) return;
    atomicAdd(&deg[eu[i]], 1.0f);
    atomicAdd(&deg[ei[i] + N_USERS], 1.0f);
}

// dinv_sqrt = rsqrt(deg>0 ? deg : 1)
__global__ void k_dinv(const float* __restrict__ deg, float* __restrict__ dinv) {
    int n = blockIdx.x * blockDim.x + threadIdx.x;
    if (n >= N_NODES) return;
    float d = deg[n];
    dinv[n] = (d > 0.0f) ? rsqrtf(d) : 1.0f;
}

// ---------------------------------------------------------------------------
// SpMM scatter: one warp per interaction; lanes 0..15 do u->item,
// lanes 16..31 do item->u. Each lane moves 4 floats via LDG.128 + red.v4.f32.
__global__ void k_scatter(const float* __restrict__ rep, float* __restrict__ out,
                          const int* __restrict__ eu, const int* __restrict__ ei,
                          const float* __restrict__ dinv, int E) {
    int w = (blockIdx.x * blockDim.x + threadIdx.x) >> 5;
    if (w >= E) return;
    int lane = threadIdx.x & 31;

    int u  = eu[w];
    int it = ei[w] + N_USERS;
    float nrm = dinv[u] * dinv[it];

    int srcN = (lane < 16) ? u  : it;
    int dstN = (lane < 16) ? it : u;
    int c = (lane & 15) << 2;  // column base 0..60 step 4

    const float4 v = *(const float4*)(rep + (size_t)srcN * EMB + c);
    float4 m = make_float4(v.x * nrm, v.y * nrm, v.z * nrm, v.w * nrm);

    float* p = out + (size_t)dstN * EMB + c;
    asm volatile("red.global.add.v4.f32 [%0], {%1, %2, %3, %4};"
                 :: "l"(p), "f"(m.x), "f"(m.y), "f"(m.z), "f"(m.w)
                 : "memory");
}

// ---------------------------------------------------------------------------
// acc = emb + rep   (first layer)
__global__ void k_accinit(float4* __restrict__ acc, const float4* __restrict__ emb,
                          const float4* __restrict__ rep) {
    size_t i = (size_t)blockIdx.x * blockDim.x + threadIdx.x;
    if (i >= (size_t)N_NODES * EMB / 4) return;
    float4 a = emb[i], b = rep[i];
    acc[i] = make_float4(a.x + b.x, a.y + b.y, a.z + b.z, a.w + b.w);
}

// acc += rep
__global__ void k_accadd(float4* __restrict__ acc, const float4* __restrict__ rep) {
    size_t i = (size_t)blockIdx.x * blockDim.x + threadIdx.x;
    if (i >= (size_t)N_NODES * EMB / 4) return;
    float4 a = acc[i], b = rep[i];
    acc[i] = make_float4(a.x + b.x, a.y + b.y, a.z + b.z, a.w + b.w);
}

// ---------------------------------------------------------------------------
// epilogue: one warp per batch row. Gathers final reps (acc * 0.25) for
// user/pos/neg and computes l2_norm_sq from the ORIGINAL embedding.
__global__ void k_gather(float* __restrict__ out, const float* __restrict__ acc,
                         const float* __restrict__ emb,
                         const int* __restrict__ users, const int* __restrict__ pos,
                         const int* __restrict__ neg) {
    int tid = blockIdx.x * blockDim.x + threadIdx.x;
    int b = tid >> 5;
    if (b >= BATCH) return;
    int lane = tid & 31;
    int c = lane * 2;

    int u = users[b];
    int p = N_USERS + pos[b];
    int g = N_USERS + neg[b];

    const float2* au = (const float2*)(acc + (size_t)u * EMB + c);
    const float2* ap = (const float2*)(acc + (size_t)p * EMB + c);
    const float2* ag = (const float2*)(acc + (size_t)g * EMB + c);
    float2 vu = *au, vp = *ap, vg = *ag;
    vu.x *= 0.25f; vu.y *= 0.25f;
    vp.x *= 0.25f; vp.y *= 0.25f;
    vg.x *= 0.25f; vg.y *= 0.25f;

    *(float2*)(out + (size_t)b * EMB + c)                    = vu;
    *(float2*)(out + (size_t)(BATCH + b) * EMB + c)          = vp;
    *(float2*)(out + (size_t)(2 * BATCH + b) * EMB + c)      = vg;

    // l2 of original embeddings
    float2 eu = *(const float2*)(emb + (size_t)u * EMB + c);
    float2 ep = *(const float2*)(emb + (size_t)p * EMB + c);
    float2 eg = *(const float2*)(emb + (size_t)g * EMB + c);
    float s = eu.x * eu.x + eu.y * eu.y
            + ep.x * ep.x + ep.y * ep.y
            + eg.x * eg.x + eg.y * eg.y;
    #pragma unroll
    for (int off = 16; off > 0; off >>= 1)
        s += __shfl_xor_sync(0xFFFFFFFFu, s, off);
    if (lane == 0)
        out[(size_t)3 * BATCH * EMB + b] = s;
}

// ---------------------------------------------------------------------------
extern "C" void kernel_launch(void* const* d_in, const int* in_sizes, int n_in,
                              void* d_out, int out_size) {
    const float* emb   = (const float*)d_in[0];
    const int*   eu    = (const int*)  d_in[1];
    const int*   ei    = (const int*)  d_in[2];
    const int*   users = (const int*)  d_in[3];
    const int*   pos   = (const int*)  d_in[4];
    const int*   neg   = (const int*)  d_in[5];
    float* out = (float*)d_out;
    const int E = in_sizes[1];

    float *repA, *repB, *acc, *deg, *dinv;
    cudaGetSymbolAddress((void**)&repA, g_repA);
    cudaGetSymbolAddress((void**)&repB, g_repB);
    cudaGetSymbolAddress((void**)&acc,  g_acc);
    cudaGetSymbolAddress((void**)&deg,  g_deg);
    cudaGetSymbolAddress((void**)&dinv, g_dinv);

    const size_t repBytes = (size_t)N_NODES * EMB * sizeof(float);
    const int TB = 256;
    const int scatterBlocks = (E + 7) / 8;               // 8 warps/block
    const int vecElems = N_NODES * EMB / 4;
    const int vecBlocks = (vecElems + TB - 1) / TB;

    // degrees + normalization
    cudaMemsetAsync(deg, 0, N_NODES * sizeof(float));
    k_hist<<<(E + TB - 1) / TB, TB>>>(eu, ei, deg, E);
    k_dinv<<<(N_NODES + TB - 1) / TB, TB>>>(deg, dinv);

    // layer 1: emb -> repA ; acc = emb + repA
    cudaMemsetAsync(repA, 0, repBytes);
    k_scatter<<<scatterBlocks, TB>>>(emb, repA, eu, ei, dinv, E);
    k_accinit<<<vecBlocks, TB>>>((float4*)acc, (const float4*)emb, (const float4*)repA);

    // layer 2: repA -> repB ; acc += repB
    cudaMemsetAsync(repB, 0, repBytes);
    k_scatter<<<scatterBlocks, TB>>>(repA, repB, eu, ei, dinv, E);
    k_accadd<<<vecBlocks, TB>>>((float4*)acc, (const float4*)repB);

    // layer 3: repB -> repA ; acc += repA
    cudaMemsetAsync(repA, 0, repBytes);
    k_scatter<<<scatterBlocks, TB>>>(repB, repA, eu, ei, dinv, E);
    k_accadd<<<vecBlocks, TB>>>((float4*)acc, (const float4*)repA);

    // epilogue gather + l2
    k_gather<<<(BATCH * 32 + TB - 1) / TB, TB>>>(out, acc, emb, users, pos, neg);
}

// round 2
// speedup vs baseline: 2.0990x; 2.0990x over previous
#include <cuda_runtime.h>
#include <cuda_bf16.h>
#include <cstdint>

#define N_USERS 100000
#define N_ITEMS 50000
#define N_NODES (N_USERS + N_ITEMS)
#define EMB 64
#define BATCH 4096
#define E_MAX 1500000

// ---- static scratch (no allocations allowed) ----
__device__ float g_repA[(size_t)N_NODES * EMB];   // 38.4 MB
__device__ float g_repB[(size_t)N_NODES * EMB];   // 38.4 MB
__device__ float g_acc [(size_t)N_NODES * EMB];   // 38.4 MB
__device__ int   g_deg   [N_NODES];
__device__ float g_dinv  [N_NODES];
__device__ int   g_rs    [N_NODES];               // row start (exclusive scan of deg)
__device__ int   g_cursor[N_NODES];
__device__ int   g_col   [2 * E_MAX];             // CSR column indices, 12 MB
__device__ int   g_bsum  [256];                   // block sums for scan

#define SCAN_T 1024
#define SCAN_BLOCKS ((N_NODES + SCAN_T - 1) / SCAN_T)   // 147

// ---------------------------------------------------------------------------
__global__ void k_hist(const int* __restrict__ eu, const int* __restrict__ ei,
                       int* __restrict__ deg, int E) {
    int i = blockIdx.x * blockDim.x + threadIdx.x;
    if (i >= E) return;
    atomicAdd(&deg[eu[i]], 1);
    atomicAdd(&deg[ei[i] + N_USERS], 1);
}

__global__ void k_dinv(const int* __restrict__ deg, float* __restrict__ dinv) {
    int n = blockIdx.x * blockDim.x + threadIdx.x;
    if (n >= N_NODES) return;
    int d = deg[n];
    dinv[n] = (d > 0) ? rsqrtf((float)d) : 1.0f;
}

// ---- 3-kernel exclusive scan of deg -> rs ----
__global__ void k_scan1(const int* __restrict__ deg, int* __restrict__ rs,
                        int* __restrict__ bsum) {
    __shared__ int sh[SCAN_T];
    int gid = blockIdx.x * SCAN_T + threadIdx.x;
    int v = (gid < N_NODES) ? deg[gid] : 0;
    sh[threadIdx.x] = v;
    __syncthreads();
    for (int off = 1; off < SCAN_T; off <<= 1) {
        int t = (threadIdx.x >= off) ? sh[threadIdx.x - off] : 0;
        __syncthreads();
        sh[threadIdx.x] += t;
        __syncthreads();
    }
    if (gid < N_NODES) rs[gid] = sh[threadIdx.x] - v;   // exclusive
    if (threadIdx.x == SCAN_T - 1) bsum[blockIdx.x] = sh[threadIdx.x];
}

__global__ void k_scan2(int* __restrict__ bsum) {
    __shared__ int sh[256];
    int v = (threadIdx.x < SCAN_BLOCKS) ? bsum[threadIdx.x] : 0;
    sh[threadIdx.x] = v;
    __syncthreads();
    for (int off = 1; off < 256; off <<= 1) {
        int t = (threadIdx.x >= off) ? sh[threadIdx.x - off] : 0;
        __syncthreads();
        sh[threadIdx.x] += t;
        __syncthreads();
    }
    if (threadIdx.x < SCAN_BLOCKS) bsum[threadIdx.x] = sh[threadIdx.x] - v;
}

__global__ void k_scan3(int* __restrict__ rs, const int* __restrict__ bsum,
                        int* __restrict__ cursor) {
    int gid = blockIdx.x * SCAN_T + threadIdx.x;
    if (gid >= N_NODES) return;
    int v = rs[gid] + bsum[blockIdx.x];
    rs[gid] = v;
    cursor[gid] = v;
}

// fill CSR column array via atomic cursors
__global__ void k_fill(const int* __restrict__ eu, const int* __restrict__ ei,
                       int* __restrict__ cursor, int* __restrict__ col, int E) {
    int i = blockIdx.x * blockDim.x + threadIdx.x;
    if (i >= E) return;
    int u  = eu[i];
    int it = ei[i] + N_USERS;
    col[atomicAdd(&cursor[u],  1)] = it;
    col[atomicAdd(&cursor[it], 1)] = u;
}

// ---------------------------------------------------------------------------
// Pull-mode SpMM layer, fused with running-sum accumulation:
//   out[n]  = dinv[n] * sum_{e in row n} dinv[col[e]] * rep[col[e]]
//   acc[n]  = accin[n] + out[n]
// One warp per node; each lane owns 2 columns (float2).
__global__ void k_pull(const float* __restrict__ rep, float* __restrict__ out,
                       const float* __restrict__ accin, float* __restrict__ acc,
                       const int* __restrict__ rs, const int* __restrict__ deg,
                       const int* __restrict__ col, const float* __restrict__ dinv) {
    int tid = blockIdx.x * blockDim.x + threadIdx.x;
    int n = tid >> 5;
    if (n >= N_NODES) return;
    int lane = tid & 31;
    int c = lane << 1;

    int beg = rs[n];
    int end = beg + deg[n];

    float sx = 0.0f, sy = 0.0f;

    // unrolled by 4 for MLP
    int e = beg;
    for (; e + 4 <= end; e += 4) {
        int s0 = col[e], s1 = col[e + 1], s2 = col[e + 2], s3 = col[e + 3];
        float w0 = dinv[s0], w1 = dinv[s1], w2 = dinv[s2], w3 = dinv[s3];
        float2 v0 = *(const float2*)(rep + (size_t)s0 * EMB + c);
        float2 v1 = *(const float2*)(rep + (size_t)s1 * EMB + c);
        float2 v2 = *(const float2*)(rep + (size_t)s2 * EMB + c);
        float2 v3 = *(const float2*)(rep + (size_t)s3 * EMB + c);
        sx += w0 * v0.x + w1 * v1.x + w2 * v2.x + w3 * v3.x;
        sy += w0 * v0.y + w1 * v1.y + w2 * v2.y + w3 * v3.y;
    }
    for (; e < end; ++e) {
        int s = col[e];
        float w = dinv[s];
        float2 v = *(const float2*)(rep + (size_t)s * EMB + c);
        sx += w * v.x;
        sy += w * v.y;
    }

    float dn = dinv[n];
    sx *= dn; sy *= dn;

    size_t ro = (size_t)n * EMB + c;
    *(float2*)(out + ro) = make_float2(sx, sy);
    float2 a = *(const float2*)(accin + ro);
    *(float2*)(acc + ro) = make_float2(a.x + sx, a.y + sy);
}

// ---------------------------------------------------------------------------
// epilogue: one warp per batch row.
__global__ void k_gather(float* __restrict__ out, const float* __restrict__ acc,
                         const float* __restrict__ emb,
                         const int* __restrict__ users, const int* __restrict__ pos,
                         const int* __restrict__ neg) {
    int tid = blockIdx.x * blockDim.x + threadIdx.x;
    int b = tid >> 5;
    if (b >= BATCH) return;
    int lane = tid & 31;
    int c = lane * 2;

    int u = users[b];
    int p = N_USERS + pos[b];
    int g = N_USERS + neg[b];

    float2 vu = *(const float2*)(acc + (size_t)u * EMB + c);
    float2 vp = *(const float2*)(acc + (size_t)p * EMB + c);
    float2 vg = *(const float2*)(acc + (size_t)g * EMB + c);
    vu.x *= 0.25f; vu.y *= 0.25f;
    vp.x *= 0.25f; vp.y *= 0.25f;
    vg.x *= 0.25f; vg.y *= 0.25f;

    *(float2*)(out + (size_t)b * EMB + c)               = vu;
    *(float2*)(out + (size_t)(BATCH + b) * EMB + c)     = vp;
    *(float2*)(out + (size_t)(2 * BATCH + b) * EMB + c) = vg;

    float2 eu = *(const float2*)(emb + (size_t)u * EMB + c);
    float2 ep = *(const float2*)(emb + (size_t)p * EMB + c);
    float2 eg = *(const float2*)(emb + (size_t)g * EMB + c);
    float s = eu.x * eu.x + eu.y * eu.y
            + ep.x * ep.x + ep.y * ep.y
            + eg.x * eg.x + eg.y * eg.y;
    #pragma unroll
    for (int off = 16; off > 0; off >>= 1)
        s += __shfl_xor_sync(0xFFFFFFFFu, s, off);
    if (lane == 0)
        out[(size_t)3 * BATCH * EMB + b] = s;
}

// ---------------------------------------------------------------------------
extern "C" void kernel_launch(void* const* d_in, const int* in_sizes, int n_in,
                              void* d_out, int out_size) {
    const float* emb   = (const float*)d_in[0];
    const int*   eu    = (const int*)  d_in[1];
    const int*   ei    = (const int*)  d_in[2];
    const int*   users = (const int*)  d_in[3];
    const int*   pos   = (const int*)  d_in[4];
    const int*   neg   = (const int*)  d_in[5];
    float* out = (float*)d_out;
    const int E = in_sizes[1];

    float *repA, *repB, *acc, *dinv;
    int *deg, *rs, *cursor, *col, *bsum;
    cudaGetSymbolAddress((void**)&repA,   g_repA);
    cudaGetSymbolAddress((void**)&repB,   g_repB);
    cudaGetSymbolAddress((void**)&acc,    g_acc);
    cudaGetSymbolAddress((void**)&dinv,   g_dinv);
    cudaGetSymbolAddress((void**)&deg,    g_deg);
    cudaGetSymbolAddress((void**)&rs,     g_rs);
    cudaGetSymbolAddress((void**)&cursor, g_cursor);
    cudaGetSymbolAddress((void**)&col,    g_col);
    cudaGetSymbolAddress((void**)&bsum,   g_bsum);

    const int TB = 256;

    // ---- CSR build ----
    cudaMemsetAsync(deg, 0, N_NODES * sizeof(int));
    k_hist<<<(E + TB - 1) / TB, TB>>>(eu, ei, deg, E);
    k_dinv<<<(N_NODES + TB - 1) / TB, TB>>>(deg, dinv);
    k_scan1<<<SCAN_BLOCKS, SCAN_T>>>(deg, rs, bsum);
    k_scan2<<<1, 256>>>(bsum);
    k_scan3<<<SCAN_BLOCKS, SCAN_T>>>(rs, bsum, cursor);
    k_fill<<<(E + TB - 1) / TB, TB>>>(eu, ei, cursor, col, E);

    // ---- 3 pull layers with fused accumulation ----
    const int pullBlocks = (N_NODES * 32 + TB - 1) / TB;
    // layer 1: emb -> repA ; acc = emb + repA
    k_pull<<<pullBlocks, TB>>>(emb,  repA, emb, acc, rs, deg, col, dinv);
    // layer 2: repA -> repB ; acc += repB
    k_pull<<<pullBlocks, TB>>>(repA, repB, acc, acc, rs, deg, col, dinv);
    // layer 3: repB -> repA ; acc += repA
    k_pull<<<pullBlocks, TB>>>(repB, repA, acc, acc, rs, deg, col, dinv);

    // ---- epilogue ----
    k_gather<<<(BATCH * 32 + TB - 1) / TB, TB>>>(out, acc, emb, users, pos, neg);
}

// round 3
// speedup vs baseline: 2.9733x; 1.4166x over previous
#include <cuda_runtime.h>
#include <cuda_bf16.h>
#include <cstdint>

#define N_USERS 100000
#define N_ITEMS 50000
#define N_NODES (N_USERS + N_ITEMS)
#define EMB 64
#define BATCH 4096
#define E_MAX 1500000

// ---- static scratch (no allocations allowed) ----
__device__ float g_repA[(size_t)N_NODES * EMB];   // 38.4 MB
__device__ float g_repB[(size_t)N_NODES * EMB];   // 38.4 MB
__device__ int   g_deg   [N_NODES];
__device__ float g_dinv  [N_NODES];
__device__ int   g_rs    [N_NODES];
__device__ int   g_cursor[N_NODES];
__device__ int   g_col   [2 * E_MAX];             // 12 MB
__device__ int   g_bsum  [256];

#define SCAN_T 1024
#define SCAN_BLOCKS ((N_NODES + SCAN_T - 1) / SCAN_T)   // 147

// ---------------------------------------------------------------------------
__global__ void k_hist(const int* __restrict__ eu, const int* __restrict__ ei,
                       int* __restrict__ deg, int E) {
    int i = blockIdx.x * blockDim.x + threadIdx.x;
    if (i >= E) return;
    atomicAdd(&deg[eu[i]], 1);
    atomicAdd(&deg[ei[i] + N_USERS], 1);
}

// scan1 also produces dinv (deg is already in registers)
__global__ void k_scan1(const int* __restrict__ deg, int* __restrict__ rs,
                        int* __restrict__ bsum, float* __restrict__ dinv) {
    __shared__ int sh[SCAN_T];
    int gid = blockIdx.x * SCAN_T + threadIdx.x;
    int v = (gid < N_NODES) ? deg[gid] : 0;
    if (gid < N_NODES) dinv[gid] = (v > 0) ? rsqrtf((float)v) : 1.0f;
    sh[threadIdx.x] = v;
    __syncthreads();
    for (int off = 1; off < SCAN_T; off <<= 1) {
        int t = (threadIdx.x >= off) ? sh[threadIdx.x - off] : 0;
        __syncthreads();
        sh[threadIdx.x] += t;
        __syncthreads();
    }
    if (gid < N_NODES) rs[gid] = sh[threadIdx.x] - v;   // exclusive
    if (threadIdx.x == SCAN_T - 1) bsum[blockIdx.x] = sh[threadIdx.x];
}

__global__ void k_scan2(int* __restrict__ bsum) {
    __shared__ int sh[256];
    int v = (threadIdx.x < SCAN_BLOCKS) ? bsum[threadIdx.x] : 0;
    sh[threadIdx.x] = v;
    __syncthreads();
    for (int off = 1; off < 256; off <<= 1) {
        int t = (threadIdx.x >= off) ? sh[threadIdx.x - off] : 0;
        __syncthreads();
        sh[threadIdx.x] += t;
        __syncthreads();
    }
    if (threadIdx.x < SCAN_BLOCKS) bsum[threadIdx.x] = sh[threadIdx.x] - v;
}

__global__ void k_scan3(int* __restrict__ rs, const int* __restrict__ bsum,
                        int* __restrict__ cursor) {
    int gid = blockIdx.x * SCAN_T + threadIdx.x;
    if (gid >= N_NODES) return;
    int v = rs[gid] + bsum[blockIdx.x];
    rs[gid] = v;
    cursor[gid] = v;
}

__global__ void k_fill(const int* __restrict__ eu, const int* __restrict__ ei,
                       int* __restrict__ cursor, int* __restrict__ col, int E) {
    int i = blockIdx.x * blockDim.x + threadIdx.x;
    if (i >= E) return;
    int u  = eu[i];
    int it = ei[i] + N_USERS;
    col[atomicAdd(&cursor[u],  1)] = it;
    col[atomicAdd(&cursor[it], 1)] = u;
}

// ---------------------------------------------------------------------------
// Warp-cooperative row pull: returns this lane's float4 partial of
//   sum_{e in [beg,end)} dinv[col[e]] * rep[col[e]][cq..cq+3]
// Half-warp per edge: lanes 0-15 take even slot, 16-31 odd slot.
// After the loop, halves are combined via shfl-xor-16; result valid on lanes 0-15.
__device__ __forceinline__ float4 row_pull(const float* __restrict__ rep,
                                           const int* __restrict__ col,
                                           const float* __restrict__ dinv,
                                           int beg, int end, int half, int cq) {
    float sx = 0.f, sy = 0.f, sz = 0.f, sw = 0.f;
    for (int e = beg; e < end; e += 4) {
        int i0 = e + half;
        int i1 = e + 2 + half;
        if (i0 < end) {
            int s = col[i0];
            float w = dinv[s];
            float4 v = *(const float4*)(rep + (size_t)s * EMB + cq);
            sx += w * v.x; sy += w * v.y; sz += w * v.z; sw += w * v.w;
        }
        if (i1 < end) {
            int s = col[i1];
            float w = dinv[s];
            float4 v = *(const float4*)(rep + (size_t)s * EMB + cq);
            sx += w * v.x; sy += w * v.y; sz += w * v.z; sw += w * v.w;
        }
    }
    sx += __shfl_xor_sync(0xFFFFFFFFu, sx, 16);
    sy += __shfl_xor_sync(0xFFFFFFFFu, sy, 16);
    sz += __shfl_xor_sync(0xFFFFFFFFu, sz, 16);
    sw += __shfl_xor_sync(0xFFFFFFFFu, sw, 16);
    return make_float4(sx, sy, sz, sw);
}

// Pull layer: out[n] = dinv[n] * sum dinv[src]*rep[src]. One warp per node.
__global__ void k_pull(const float* __restrict__ rep, float* __restrict__ out,
                       const int* __restrict__ rs, const int* __restrict__ deg,
                       const int* __restrict__ col, const float* __restrict__ dinv) {
    int tid = blockIdx.x * blockDim.x + threadIdx.x;
    int n = tid >> 5;
    if (n >= N_NODES) return;
    int lane = tid & 31;
    int half = lane >> 4;
    int cq = (lane & 15) << 2;

    int beg = rs[n];
    int end = beg + deg[n];

    float4 s = row_pull(rep, col, dinv, beg, end, half, cq);

    if (lane < 16) {
        float dn = dinv[n];
        s.x *= dn; s.y *= dn; s.z *= dn; s.w *= dn;
        *(float4*)(out + (size_t)n * EMB + cq) = s;
    }
}

// ---------------------------------------------------------------------------
// Fused layer-3 + epilogue. One warp per (role, batch-row):
//   r3 = dinv[n] * sum dinv[src]*repB[src]   (pull on demand)
//   out_row = (emb[n] + repA[n] + repB[n] + r3) * 0.25
// role 0 warps additionally compute l2_norm_sq over original embeddings.
__global__ void k_final(float* __restrict__ out,
                        const float* __restrict__ emb,
                        const float* __restrict__ repA,
                        const float* __restrict__ repB,
                        const int* __restrict__ rs, const int* __restrict__ deg,
                        const int* __restrict__ col, const float* __restrict__ dinv,
                        const int* __restrict__ users, const int* __restrict__ pos,
                        const int* __restrict__ neg) {
    int tid = blockIdx.x * blockDim.x + threadIdx.x;
    int w = tid >> 5;
    if (w >= 3 * BATCH) return;
    int lane = tid & 31;
    int half = lane >> 4;
    int cq = (lane & 15) << 2;

    int role = w / BATCH;
    int b = w - role * BATCH;
    int n = (role == 0) ? users[b]
          : (role == 1) ? (N_USERS + pos[b])
                        : (N_USERS + neg[b]);

    int beg = rs[n];
    int end = beg + deg[n];

    float4 s = row_pull(repB, col, dinv, beg, end, half, cq);

    if (lane < 16) {
        float dn = dinv[n];
        size_t ro = (size_t)n * EMB + cq;
        float4 e4 = *(const float4*)(emb  + ro);
        float4 a4 = *(const float4*)(repA + ro);
        float4 b4 = *(const float4*)(repB + ro);
        float4 r;
        r.x = (e4.x + a4.x + b4.x + s.x * dn) * 0.25f;
        r.y = (e4.y + a4.y + b4.y + s.y * dn) * 0.25f;
        r.z = (e4.z + a4.z + b4.z + s.z * dn) * 0.25f;
        r.w = (e4.w + a4.w + b4.w + s.w * dn) * 0.25f;
        *(float4*)(out + (size_t)(role * BATCH + b) * EMB + cq) = r;
    }

    if (role == 0) {
        // l2 over emb[u], emb[pos], emb[neg]; all 32 lanes, 2 floats each
        int p = N_USERS + pos[b];
        int g = N_USERS + neg[b];
        int c = lane * 2;
        float2 eu = *(const float2*)(emb + (size_t)n * EMB + c);
        float2 ep = *(const float2*)(emb + (size_t)p * EMB + c);
        float2 eg = *(const float2*)(emb + (size_t)g * EMB + c);
        float sum = eu.x * eu.x + eu.y * eu.y
                  + ep.x * ep.x + ep.y * ep.y
                  + eg.x * eg.x + eg.y * eg.y;
        #pragma unroll
        for (int off = 16; off > 0; off >>= 1)
            sum += __shfl_xor_sync(0xFFFFFFFFu, sum, off);
        if (lane == 0)
            out[(size_t)3 * BATCH * EMB + b] = sum;
    }
}

// ---------------------------------------------------------------------------
extern "C" void kernel_launch(void* const* d_in, const int* in_sizes, int n_in,
                              void* d_out, int out_size) {
    const float* emb   = (const float*)d_in[0];
    const int*   eu    = (const int*)  d_in[1];
    const int*   ei    = (const int*)  d_in[2];
    const int*   users = (const int*)  d_in[3];
    const int*   pos   = (const int*)  d_in[4];
    const int*   neg   = (const int*)  d_in[5];
    float* out = (float*)d_out;
    const int E = in_sizes[1];

    float *repA, *repB, *dinv;
    int *deg, *rs, *cursor, *col, *bsum;
    cudaGetSymbolAddress((void**)&repA,   g_repA);
    cudaGetSymbolAddress((void**)&repB,   g_repB);
    cudaGetSymbolAddress((void**)&dinv,   g_dinv);
    cudaGetSymbolAddress((void**)&deg,    g_deg);
    cudaGetSymbolAddress((void**)&rs,     g_rs);
    cudaGetSymbolAddress((void**)&cursor, g_cursor);
    cudaGetSymbolAddress((void**)&col,    g_col);
    cudaGetSymbolAddress((void**)&bsum,   g_bsum);

    const int TB = 256;

    // ---- CSR build ----
    cudaMemsetAsync(deg, 0, N_NODES * sizeof(int));
    k_hist<<<(E + TB - 1) / TB, TB>>>(eu, ei, deg, E);
    k_scan1<<<SCAN_BLOCKS, SCAN_T>>>(deg, rs, bsum, dinv);
    k_scan2<<<1, 256>>>(bsum);
    k_scan3<<<SCAN_BLOCKS, SCAN_T>>>(rs, bsum, cursor);
    k_fill<<<(E + TB - 1) / TB, TB>>>(eu, ei, cursor, col, E);

    // ---- layers 1 & 2: full-table pulls (no acc table needed) ----
    const int pullBlocks = (N_NODES * 32 + TB - 1) / TB;
    k_pull<<<pullBlocks, TB>>>(emb,  repA, rs, deg, col, dinv);   // r1
    k_pull<<<pullBlocks, TB>>>(repA, repB, rs, deg, col, dinv);   // r2

    // ---- layer 3 fused with epilogue: only batch nodes ----
    const int finalBlocks = (3 * BATCH * 32 + TB - 1) / TB;
    k_final<<<finalBlocks, TB>>>(out, emb, repA, repB, rs, deg, col, dinv,
                                 users, pos, neg);
}

// round 4
// speedup vs baseline: 3.0016x; 1.0095x over previous
#include <cuda_runtime.h>
#include <cuda_fp16.h>
#include <cstdint>

#define N_USERS 100000
#define N_ITEMS 50000
#define N_NODES (N_USERS + N_ITEMS)
#define EMB 64
#define BATCH 4096
#define E_MAX 1500000

// ---- static scratch (no allocations allowed) ----
__device__ __half g_q0[(size_t)N_NODES * EMB];    // 19.2 MB  dinv*emb
__device__ __half g_q1[(size_t)N_NODES * EMB];    // 19.2 MB  dinv*rep1
__device__ __half g_q2[(size_t)N_NODES * EMB];    // 19.2 MB  dinv*rep2
__device__ int    g_deg   [N_NODES];
__device__ float  g_dinv  [N_NODES];
__device__ int    g_rs    [N_NODES];
__device__ int    g_cursor[N_NODES];
__device__ int    g_col   [2 * E_MAX + 16];       // padded for int4 over-read
__device__ int    g_bsum  [256];

#define SCAN_T 1024
#define SCAN_BLOCKS ((N_NODES + SCAN_T - 1) / SCAN_T)   // 147

// ---------------------------------------------------------------------------
__global__ void k_hist(const int* __restrict__ eu, const int* __restrict__ ei,
                       int* __restrict__ deg, int E) {
    int i = blockIdx.x * blockDim.x + threadIdx.x;
    if (i >= E) return;
    atomicAdd(&deg[eu[i]], 1);
    atomicAdd(&deg[ei[i] + N_USERS], 1);
}

__global__ void k_scan1(const int* __restrict__ deg, int* __restrict__ rs,
                        int* __restrict__ bsum, float* __restrict__ dinv) {
    __shared__ int sh[SCAN_T];
    int gid = blockIdx.x * SCAN_T + threadIdx.x;
    int v = (gid < N_NODES) ? deg[gid] : 0;
    if (gid < N_NODES) dinv[gid] = (v > 0) ? rsqrtf((float)v) : 1.0f;
    sh[threadIdx.x] = v;
    __syncthreads();
    for (int off = 1; off < SCAN_T; off <<= 1) {
        int t = (threadIdx.x >= off) ? sh[threadIdx.x - off] : 0;
        __syncthreads();
        sh[threadIdx.x] += t;
        __syncthreads();
    }
    if (gid < N_NODES) rs[gid] = sh[threadIdx.x] - v;   // exclusive
    if (threadIdx.x == SCAN_T - 1) bsum[blockIdx.x] = sh[threadIdx.x];
}

__global__ void k_scan2(int* __restrict__ bsum) {
    __shared__ int sh[256];
    int v = (threadIdx.x < SCAN_BLOCKS) ? bsum[threadIdx.x] : 0;
    sh[threadIdx.x] = v;
    __syncthreads();
    for (int off = 1; off < 256; off <<= 1) {
        int t = (threadIdx.x >= off) ? sh[threadIdx.x - off] : 0;
        __syncthreads();
        sh[threadIdx.x] += t;
        __syncthreads();
    }
    if (threadIdx.x < SCAN_BLOCKS) bsum[threadIdx.x] = sh[threadIdx.x] - v;
}

__global__ void k_scan3(int* __restrict__ rs, const int* __restrict__ bsum,
                        int* __restrict__ cursor) {
    int gid = blockIdx.x * SCAN_T + threadIdx.x;
    if (gid >= N_NODES) return;
    int v = rs[gid] + bsum[blockIdx.x];
    rs[gid] = v;
    cursor[gid] = v;
}

__global__ void k_fill(const int* __restrict__ eu, const int* __restrict__ ei,
                       int* __restrict__ cursor, int* __restrict__ col, int E) {
    int i = blockIdx.x * blockDim.x + threadIdx.x;
    if (i >= E) return;
    int u  = eu[i];
    int it = ei[i] + N_USERS;
    col[atomicAdd(&cursor[u],  1)] = it;
    col[atomicAdd(&cursor[it], 1)] = u;
}

// q0 = dinv * emb, stored fp16
__global__ void k_q0(const float4* __restrict__ emb, uint2* __restrict__ q0,
                     const float* __restrict__ dinv) {
    int i = blockIdx.x * blockDim.x + threadIdx.x;
    if (i >= N_NODES * (EMB / 4)) return;
    float d = dinv[i >> 4];
    float4 v = emb[i];
    __half2 a = __floats2half2_rn(v.x * d, v.y * d);
    __half2 b = __floats2half2_rn(v.z * d, v.w * d);
    uint2 o;
    o.x = *(unsigned*)&a;
    o.y = *(unsigned*)&b;
    q0[i] = o;
}

// ---------------------------------------------------------------------------
// Warp-cooperative fp16 row gather-sum.
// Quarter-warp per edge; lane = 8*quarter + sub; lane loads uint4 (8 halfs)
// covering columns sub*8..sub*8+7. Iteration covers 16 edges; each lane loads
// an int4 of cols for its quarter once per iteration.
// On return, EVERY lane holds the full-row sum for its 8 columns in acc[8].
__device__ __forceinline__ void row_sum_h(const __half* __restrict__ qin,
                                          const int* __restrict__ col,
                                          int beg, int end, int lane,
                                          float acc[8]) {
    int quarter = lane >> 3;
    int sub = lane & 7;
    #pragma unroll
    for (int k = 0; k < 8; ++k) acc[k] = 0.0f;

    for (int e0 = (beg & ~3); e0 < end; e0 += 16) {
        int base = e0 + 4 * quarter;
        int4 c4 = *(const int4*)(col + base);      // 16B aligned; array padded
        int cs[4] = {c4.x, c4.y, c4.z, c4.w};
        #pragma unroll
        for (int j = 0; j < 4; ++j) {
            int idx = base + j;
            if (idx >= beg && idx < end) {
                const uint4* qp = (const uint4*)(qin + (size_t)cs[j] * EMB) + sub;
                uint4 qv = *qp;
                const __half2* hp = (const __half2*)&qv;
                float2 f0 = __half22float2(hp[0]);
                float2 f1 = __half22float2(hp[1]);
                float2 f2 = __half22float2(hp[2]);
                float2 f3 = __half22float2(hp[3]);
                acc[0] += f0.x; acc[1] += f0.y;
                acc[2] += f1.x; acc[3] += f1.y;
                acc[4] += f2.x; acc[5] += f2.y;
                acc[6] += f3.x; acc[7] += f3.y;
            }
        }
    }
    // combine the 4 quarters; after this every lane has the full sums
    #pragma unroll
    for (int k = 0; k < 8; ++k) {
        acc[k] += __shfl_xor_sync(0xFFFFFFFFu, acc[k], 8);
        acc[k] += __shfl_xor_sync(0xFFFFFFFFu, acc[k], 16);
    }
}

// Pull layer on q-tables: qout[n] = dinv[n]^2 * sum_{s in N(n)} qin[s]
__global__ void k_pull_h(const __half* __restrict__ qin, __half* __restrict__ qout,
                         const int* __restrict__ rs, const int* __restrict__ deg,
                         const int* __restrict__ col, const float* __restrict__ dinv) {
    int tid = blockIdx.x * blockDim.x + threadIdx.x;
    int n = tid >> 5;
    if (n >= N_NODES) return;
    int lane = tid & 31;

    int beg = rs[n];
    int end = beg + deg[n];

    float acc[8];
    row_sum_h(qin, col, beg, end, lane, acc);

    if (lane < 8) {
        float d = dinv[n];
        float s = d * d;
        __half2 h0 = __floats2half2_rn(acc[0] * s, acc[1] * s);
        __half2 h1 = __floats2half2_rn(acc[2] * s, acc[3] * s);
        __half2 h2 = __floats2half2_rn(acc[4] * s, acc[5] * s);
        __half2 h3 = __floats2half2_rn(acc[6] * s, acc[7] * s);
        uint4 o;
        o.x = *(unsigned*)&h0; o.y = *(unsigned*)&h1;
        o.z = *(unsigned*)&h2; o.w = *(unsigned*)&h3;
        *((uint4*)(qout + (size_t)n * EMB) + lane) = o;
    }
}

// ---------------------------------------------------------------------------
// Fused layer-3 + epilogue. One warp per (role, batch-row), n = node id:
//   rep3 = dinv[n] * sum q2[s]
//   final = 0.25 * ( emb[n] + sq*(q1[n]+q2[n]) + rep3 ),  sq = deg>0? sqrt(deg):1
__global__ void k_final(float* __restrict__ out,
                        const float* __restrict__ emb,
                        const __half* __restrict__ q1,
                        const __half* __restrict__ q2,
                        const int* __restrict__ rs, const int* __restrict__ deg,
                        const int* __restrict__ col, const float* __restrict__ dinv,
                        const int* __restrict__ users, const int* __restrict__ pos,
                        const int* __restrict__ neg) {
    int tid = blockIdx.x * blockDim.x + threadIdx.x;
    int w = tid >> 5;
    if (w >= 3 * BATCH) return;
    int lane = tid & 31;

    int role = w / BATCH;
    int b = w - role * BATCH;
    int n = (role == 0) ? users[b]
          : (role == 1) ? (N_USERS + pos[b])
                        : (N_USERS + neg[b]);

    int dg = deg[n];
    int beg = rs[n];
    int end = beg + dg;

    float acc[8];
    row_sum_h(q2, col, beg, end, lane, acc);

    if (lane < 8) {
        float d = dinv[n];
        float sq = (dg > 0) ? sqrtf((float)dg) : 1.0f;
        size_t ro = (size_t)n * EMB + lane * 8;

        float4 e0 = *(const float4*)(emb + ro);
        float4 e1 = *(const float4*)(emb + ro + 4);
        uint4 a1 = *((const uint4*)(q1 + (size_t)n * EMB) + lane);
        uint4 a2 = *((const uint4*)(q2 + (size_t)n * EMB) + lane);
        const __half2* h1 = (const __half2*)&a1;
        const __half2* h2 = (const __half2*)&a2;

        float r[8];
        #pragma unroll
        for (int k = 0; k < 4; ++k) {
            float2 f1 = __half22float2(h1[k]);
            float2 f2 = __half22float2(h2[k]);
            r[2*k]   = sq * (f1.x + f2.x) + d * acc[2*k];
            r[2*k+1] = sq * (f1.y + f2.y) + d * acc[2*k+1];
        }
        float4 o0, o1;
        o0.x = (e0.x + r[0]) * 0.25f; o0.y = (e0.y + r[1]) * 0.25f;
        o0.z = (e0.z + r[2]) * 0.25f; o0.w = (e0.w + r[3]) * 0.25f;
        o1.x = (e1.x + r[4]) * 0.25f; o1.y = (e1.y + r[5]) * 0.25f;
        o1.z = (e1.z + r[6]) * 0.25f; o1.w = (e1.w + r[7]) * 0.25f;

        size_t wo = (size_t)(role * BATCH + b) * EMB + lane * 8;
        *(float4*)(out + wo)     = o0;
        *(float4*)(out + wo + 4) = o1;
    }

    if (role == 0) {
        int p = N_USERS + pos[b];
        int g = N_USERS + neg[b];
        int c = lane * 2;
        float2 eu = *(const float2*)(emb + (size_t)n * EMB + c);
        float2 ep = *(const float2*)(emb + (size_t)p * EMB + c);
        float2 eg = *(const float2*)(emb + (size_t)g * EMB + c);
        float sum = eu.x * eu.x + eu.y * eu.y
                  + ep.x * ep.x + ep.y * ep.y
                  + eg.x * eg.x + eg.y * eg.y;
        #pragma unroll
        for (int off = 16; off > 0; off >>= 1)
            sum += __shfl_xor_sync(0xFFFFFFFFu, sum, off);
        if (lane == 0)
            out[(size_t)3 * BATCH * EMB + b] = sum;
    }
}

// ---------------------------------------------------------------------------
extern "C" void kernel_launch(void* const* d_in, const int* in_sizes, int n_in,
                              void* d_out, int out_size) {
    const float* emb   = (const float*)d_in[0];
    const int*   eu    = (const int*)  d_in[1];
    const int*   ei    = (const int*)  d_in[2];
    const int*   users = (const int*)  d_in[3];
    const int*   pos   = (const int*)  d_in[4];
    const int*   neg   = (const int*)  d_in[5];
    float* out = (float*)d_out;
    const int E = in_sizes[1];

    __half *q0, *q1, *q2;
    float *dinv;
    int *deg, *rs, *cursor, *col, *bsum;
    cudaGetSymbolAddress((void**)&q0,     g_q0);
    cudaGetSymbolAddress((void**)&q1,     g_q1);
    cudaGetSymbolAddress((void**)&q2,     g_q2);
    cudaGetSymbolAddress((void**)&dinv,   g_dinv);
    cudaGetSymbolAddress((void**)&deg,    g_deg);
    cudaGetSymbolAddress((void**)&rs,     g_rs);
    cudaGetSymbolAddress((void**)&cursor, g_cursor);
    cudaGetSymbolAddress((void**)&col,    g_col);
    cudaGetSymbolAddress((void**)&bsum,   g_bsum);

    const int TB = 256;

    // ---- CSR build ----
    cudaMemsetAsync(deg, 0, N_NODES * sizeof(int));
    k_hist<<<(E + TB - 1) / TB, TB>>>(eu, ei, deg, E);
    k_scan1<<<SCAN_BLOCKS, SCAN_T>>>(deg, rs, bsum, dinv);
    k_scan2<<<1, 256>>>(bsum);
    k_scan3<<<SCAN_BLOCKS, SCAN_T>>>(rs, bsum, cursor);
    k_fill<<<(E + TB - 1) / TB, TB>>>(eu, ei, cursor, col, E);

    // ---- q0 = dinv*emb (fp16) ----
    const int q0Elems = N_NODES * (EMB / 4);
    k_q0<<<(q0Elems + TB - 1) / TB, TB>>>((const float4*)emb, (uint2*)q0, dinv);

    // ---- layers 1 & 2 on q-tables ----
    const int pullBlocks = (N_NODES * 32 + TB - 1) / TB;
    k_pull_h<<<pullBlocks, TB>>>(q0, q1, rs, deg, col, dinv);
    k_pull_h<<<pullBlocks, TB>>>(q1, q2, rs, deg, col, dinv);

    // ---- fused layer 3 + epilogue ----
    const int finalBlocks = (3 * BATCH * 32 + TB - 1) / TB;
    k_final<<<finalBlocks, TB>>>(out, emb, q1, q2, rs, deg, col, dinv,
                                 users, pos, neg);
}